// round 1
// baseline (speedup 1.0000x reference)
#include <cuda_runtime.h>
#include <math.h>

// GCRNN cell: B=64, N=4096, F=2, U=16, S=2
// Pass 1: D1[s][m][b*18+c] = sum_n S_s[m][n] * X1[n][b*18+c]   (c: 0,1=feats, 2..17=state)
// Epi 1 : hs(36) -> r,u gates; XT2[m][b*16+u] = r * prev
// Pass 2: D2[s][m][b*16+u] = sum_n S_s[m][n] * XT2[n][b*16+u]
// Epi 2 : c = tanh([h, c_state] @ ck); z = u*prev + (1-u)*c -> out[b][m*16+u]

#define NN 4096
#define NCOL1 1152   // B*18
#define NCOL2 1024   // B*16

__device__ float g_XT1[NN * NCOL1];
__device__ float g_D1[2 * NN * NCOL1];
__device__ float g_XT2[NN * NCOL2];
__device__ float g_D2[2 * NN * NCOL2];
__device__ float g_U[NN * NCOL2];
__device__ float g_H[NN * 256];

// ---------------------------------------------------------------- pack ----
__global__ __launch_bounds__(256) void pack1(const float* __restrict__ inputs,
                                             const float* __restrict__ state) {
    int idx = blockIdx.x * blockDim.x + threadIdx.x;   // 1152*4096 elements
    int n = idx & 4095;
    int col = idx >> 12;              // 0..1151
    int b = col / 18;
    int c = col - b * 18;
    float v = (c < 2) ? inputs[b * 8192 + c * 4096 + n]
                      : state[b * 65536 + (c - 2) * 4096 + n];
    g_XT1[n * NCOL1 + col] = v;
}

// ---------------------------------------------------------------- gemm ----
__device__ __forceinline__ unsigned f2tf(float x) {
    unsigned u;
    asm("cvt.rna.tf32.f32 %0, %1;" : "=r"(u) : "f"(x));
    return u;
}

// C[z][m][col] = sum_n A_z[m][n] * X[n][col], A_z = (z ? S1 : S0)
// BM=128 BN=64 BK=32, 256 threads, warp grid 4(m) x 2(n), warp tile 32x32
__global__ __launch_bounds__(256) void gemm_diffuse(
    const float* __restrict__ S0, const float* __restrict__ S1,
    const float* __restrict__ X, float* __restrict__ C, int ncol)
{
    __shared__ float As[128][36];   // pad 32->36: conflict-free frag loads
    __shared__ float Bs[32][68];    // pad 64->68

    const float* A = blockIdx.z ? S1 : S0;
    float* Cb = C + (size_t)blockIdx.z * NN * ncol;
    const int m0 = blockIdx.x * 128;
    const int c0 = blockIdx.y * 64;
    const int tid = threadIdx.x;
    const int lane = tid & 31;
    const int warp = tid >> 5;
    const int wm = warp & 3;        // 0..3 -> m offset
    const int wn = warp >> 2;       // 0..1 -> n offset

    float acc[2][4][4];
    #pragma unroll
    for (int mi = 0; mi < 2; mi++)
        #pragma unroll
        for (int ni = 0; ni < 4; ni++)
            #pragma unroll
            for (int t = 0; t < 4; t++) acc[mi][ni][t] = 0.f;

    for (int k0 = 0; k0 < 4096; k0 += 32) {
        // stage A: 128x32 floats = 1024 float4, 4 per thread
        #pragma unroll
        for (int i = 0; i < 4; i++) {
            int q = tid + i * 256;
            int r = q >> 3, c4 = q & 7;
            float4 v = *(const float4*)(A + (size_t)(m0 + r) * 4096 + k0 + c4 * 4);
            As[r][c4 * 4 + 0] = __uint_as_float(f2tf(v.x));
            As[r][c4 * 4 + 1] = __uint_as_float(f2tf(v.y));
            As[r][c4 * 4 + 2] = __uint_as_float(f2tf(v.z));
            As[r][c4 * 4 + 3] = __uint_as_float(f2tf(v.w));
        }
        // stage B: 32x64 floats = 512 float4, 2 per thread
        #pragma unroll
        for (int i = 0; i < 2; i++) {
            int q = tid + i * 256;
            int r = q >> 4, c4 = q & 15;
            float4 v = *(const float4*)(X + (size_t)(k0 + r) * ncol + c0 + c4 * 4);
            Bs[r][c4 * 4 + 0] = __uint_as_float(f2tf(v.x));
            Bs[r][c4 * 4 + 1] = __uint_as_float(f2tf(v.y));
            Bs[r][c4 * 4 + 2] = __uint_as_float(f2tf(v.z));
            Bs[r][c4 * 4 + 3] = __uint_as_float(f2tf(v.w));
        }
        __syncthreads();

        #pragma unroll
        for (int kk = 0; kk < 4; kk++) {
            const int ks = kk * 8;
            unsigned a[2][4], bfr[4][2];
            #pragma unroll
            for (int mi = 0; mi < 2; mi++) {
                int row = wm * 32 + mi * 16 + (lane >> 2);
                int ck_ = ks + (lane & 3);
                a[mi][0] = __float_as_uint(As[row][ck_]);
                a[mi][1] = __float_as_uint(As[row + 8][ck_]);
                a[mi][2] = __float_as_uint(As[row][ck_ + 4]);
                a[mi][3] = __float_as_uint(As[row + 8][ck_ + 4]);
            }
            #pragma unroll
            for (int ni = 0; ni < 4; ni++) {
                int bn = wn * 32 + ni * 8 + (lane >> 2);
                bfr[ni][0] = __float_as_uint(Bs[ks + (lane & 3)][bn]);
                bfr[ni][1] = __float_as_uint(Bs[ks + 4 + (lane & 3)][bn]);
            }
            #pragma unroll
            for (int mi = 0; mi < 2; mi++)
                #pragma unroll
                for (int ni = 0; ni < 4; ni++) {
                    asm volatile(
                        "mma.sync.aligned.m16n8k8.row.col.f32.tf32.tf32.f32 "
                        "{%0,%1,%2,%3}, {%4,%5,%6,%7}, {%8,%9}, {%0,%1,%2,%3};\n"
                        : "+f"(acc[mi][ni][0]), "+f"(acc[mi][ni][1]),
                          "+f"(acc[mi][ni][2]), "+f"(acc[mi][ni][3])
                        : "r"(a[mi][0]), "r"(a[mi][1]), "r"(a[mi][2]), "r"(a[mi][3]),
                          "r"(bfr[ni][0]), "r"(bfr[ni][1]));
                }
        }
        __syncthreads();
    }

    #pragma unroll
    for (int mi = 0; mi < 2; mi++) {
        int r0 = m0 + wm * 32 + mi * 16 + (lane >> 2);
        #pragma unroll
        for (int ni = 0; ni < 4; ni++) {
            int cc = c0 + wn * 32 + ni * 8 + (lane & 3) * 2;
            *(float2*)&Cb[(size_t)r0 * ncol + cc] =
                make_float2(acc[mi][ni][0], acc[mi][ni][1]);
            *(float2*)&Cb[(size_t)(r0 + 8) * ncol + cc] =
                make_float2(acc[mi][ni][2], acc[mi][ni][3]);
        }
    }
}

// ---------------------------------------------------------------- epi 1 ---
__global__ __launch_bounds__(256) void epi1(const float* __restrict__ state,
                                            const float* __restrict__ rk,
                                            const float* __restrict__ uk)
{
    __shared__ float srk[576], suk[576];
    for (int i = threadIdx.x; i < 576; i += 256) {
        srk[i] = rk[i];
        suk[i] = uk[i];
    }
    __syncthreads();

    int idx = blockIdx.x * blockDim.x + threadIdx.x;  // b*4096 + m
    int m = idx & 4095;
    int b = idx >> 12;

    float hs[36];
    #pragma unroll
    for (int s = 0; s < 2; s++) {
        const float* d = g_D1 + ((size_t)s * NN + m) * NCOL1 + b * 18;
        hs[s * 2 + 0] = d[0];
        hs[s * 2 + 1] = d[1];
        #pragma unroll
        for (int u = 0; u < 16; u++) hs[4 + s * 16 + u] = d[2 + u];
    }

    float aR[16], aU[16];
    #pragma unroll
    for (int u = 0; u < 16; u++) { aR[u] = 0.f; aU[u] = 0.f; }
    #pragma unroll
    for (int j = 0; j < 36; j++) {
        float h = hs[j];
        #pragma unroll
        for (int u = 0; u < 16; u++) {
            aR[u] = fmaf(h, srk[j * 16 + u], aR[u]);
            aU[u] = fmaf(h, suk[j * 16 + u], aU[u]);
        }
    }
    #pragma unroll
    for (int u = 0; u < 16; u++) {
        float r  = 1.f / (1.f + expf(-aR[u]));
        float uu = 1.f / (1.f + expf(-aU[u]));
        float pv = state[b * 65536 + u * 4096 + m];
        g_XT2[m * NCOL2 + b * 16 + u] = r * pv;
        g_U  [m * NCOL2 + b * 16 + u] = uu;
    }
    #pragma unroll
    for (int j = 0; j < 4; j++) g_H[m * 256 + b * 4 + j] = hs[j];
}

// ---------------------------------------------------------------- epi 2 ---
__global__ __launch_bounds__(256) void epi2(const float* __restrict__ state,
                                            const float* __restrict__ ck,
                                            float* __restrict__ out)
{
    __shared__ float sck[576];
    for (int i = threadIdx.x; i < 576; i += 256) sck[i] = ck[i];
    __syncthreads();

    int idx = blockIdx.x * blockDim.x + threadIdx.x;  // b*4096 + m
    int m = idx & 4095;
    int b = idx >> 12;

    float hs[36];
    #pragma unroll
    for (int j = 0; j < 4; j++) hs[j] = g_H[m * 256 + b * 4 + j];
    #pragma unroll
    for (int s = 0; s < 2; s++) {
        const float* d = g_D2 + ((size_t)s * NN + m) * NCOL2 + b * 16;
        #pragma unroll
        for (int u = 0; u < 16; u++) hs[4 + s * 16 + u] = d[u];
    }

    float aC[16];
    #pragma unroll
    for (int u = 0; u < 16; u++) aC[u] = 0.f;
    #pragma unroll
    for (int j = 0; j < 36; j++) {
        float h = hs[j];
        #pragma unroll
        for (int u = 0; u < 16; u++) aC[u] = fmaf(h, sck[j * 16 + u], aC[u]);
    }
    #pragma unroll
    for (int u = 0; u < 16; u++) {
        float c  = tanhf(aC[u]);
        float uu = g_U[m * NCOL2 + b * 16 + u];
        float pv = state[b * 65536 + u * 4096 + m];
        out[b * 65536 + m * 16 + u] = uu * pv + (1.f - uu) * c;
    }
}

// -------------------------------------------------------------- launch ----
extern "C" void kernel_launch(void* const* d_in, const int* in_sizes, int n_in,
                              void* d_out, int out_size) {
    const float* inputs = (const float*)d_in[0];
    const float* state  = (const float*)d_in[1];
    const float* s0     = (const float*)d_in[2];
    const float* s1     = (const float*)d_in[3];
    const float* rk     = (const float*)d_in[4];
    const float* uk     = (const float*)d_in[5];
    const float* ck     = (const float*)d_in[6];
    float* out = (float*)d_out;

    float *xt1, *d1, *xt2, *d2;
    cudaGetSymbolAddress((void**)&xt1, g_XT1);
    cudaGetSymbolAddress((void**)&d1,  g_D1);
    cudaGetSymbolAddress((void**)&xt2, g_XT2);
    cudaGetSymbolAddress((void**)&d2,  g_D2);

    pack1<<<(NN * NCOL1) / 256, 256>>>(inputs, state);
    gemm_diffuse<<<dim3(32, NCOL1 / 64, 2), 256>>>(s0, s1, xt1, d1, NCOL1);
    epi1<<<(64 * NN) / 256, 256>>>(state, rk, uk);
    gemm_diffuse<<<dim3(32, NCOL2 / 64, 2), 256>>>(s0, s1, xt2, d2, NCOL2);
    epi2<<<(64 * NN) / 256, 256>>>(state, ck, out);
}

// round 3
// speedup vs baseline: 2.3269x; 2.3269x over previous
#include <cuda_runtime.h>
#include <cuda_bf16.h>
#include <cstdint>
#include <math.h>

// GCRNN cell: B=64, N=4096, F=2, U=16, S=2
// bf16 tensor-core GEMM (m16n8k16) with cp.async 3-stage pipeline.
// X operands stored bf16 COLUMN-major [col][n] so B-tile staging is a pure copy.

#define NN 4096
#define NCOL1 1152   // B*18
#define NCOL2 1024   // B*16
#define BK 64
#define NT (NN / BK)          // 64 k-tiles
#define STAGES 3
// smem per stage: A 128 rows x 72 bf16, B 64 rows x 72 bf16
#define A_ROW_W 72            // bf16 elems per smem row (64 + 8 pad; 144B)
#define STAGE_ELEMS (128 * A_ROW_W + 64 * A_ROW_W)   // 13824 bf16
#define SMEM_BYTES (STAGES * STAGE_ELEMS * 2)        // 82944 B

__device__ __nv_bfloat16 g_Sbf[2ull * NN * NN];      // supports, bf16 row-major
__device__ __nv_bfloat16 g_X1[(size_t)NCOL1 * NN];   // col-major [col][n]
__device__ __nv_bfloat16 g_X2[(size_t)NCOL2 * NN];   // col-major [col][n]
__device__ float g_D1[2ull * NN * NCOL1];
__device__ float g_D2[2ull * NN * NCOL2];
__device__ float g_U[(size_t)NN * NCOL2];
__device__ float g_H[(size_t)NN * 256];

// ------------------------------------------------------------ convert ----
__global__ __launch_bounds__(256) void conv_sup(const float* __restrict__ S0,
                                                const float* __restrict__ S1) {
    const float* S = blockIdx.y ? S1 : S0;
    __nv_bfloat16* D = g_Sbf + (size_t)blockIdx.y * NN * NN;
    size_t idx = (size_t)blockIdx.x * 256 + threadIdx.x;   // 2M iters per support
    float4 v0 = ((const float4*)S)[idx * 2];
    float4 v1 = ((const float4*)S)[idx * 2 + 1];
    __nv_bfloat162 p[4];
    p[0] = __floats2bfloat162_rn(v0.x, v0.y);
    p[1] = __floats2bfloat162_rn(v0.z, v0.w);
    p[2] = __floats2bfloat162_rn(v1.x, v1.y);
    p[3] = __floats2bfloat162_rn(v1.z, v1.w);
    ((uint4*)D)[idx] = *(uint4*)p;
}

// --------------------------------------------------------------- pack ----
__global__ __launch_bounds__(256) void pack1(const float* __restrict__ inputs,
                                             const float* __restrict__ state) {
    int idx = blockIdx.x * blockDim.x + threadIdx.x;
    int n = idx & 4095;
    int col = idx >> 12;              // 0..1151
    int b = col / 18;
    int c = col - b * 18;
    float v = (c < 2) ? inputs[b * 8192 + c * 4096 + n]
                      : state[b * 65536 + (c - 2) * 4096 + n];
    g_X1[(size_t)col * NN + n] = __float2bfloat16_rn(v);
}

// --------------------------------------------------------------- gemm ----
__device__ __forceinline__ void cp16(void* dst, const void* src) {
    unsigned s = (unsigned)__cvta_generic_to_shared(dst);
    asm volatile("cp.async.cg.shared.global [%0], [%1], 16;\n" :: "r"(s), "l"(src));
}

// C[z][m][col] = sum_n S_z[m][n] * Xcm[col][n]
// BM=128 BN=64 BK=64, 256 thr, warps 4(m) x 2(n), warp tile 32x32, m16n8k16 bf16
__global__ __launch_bounds__(256) void gemm_bf16(
    const __nv_bfloat16* __restrict__ X, float* __restrict__ C, int ncol)
{
    extern __shared__ __align__(16) char smem[];

    const __nv_bfloat16* A = g_Sbf + (size_t)blockIdx.z * NN * NN;
    float* Cb = C + (size_t)blockIdx.z * NN * ncol;
    const int m0 = blockIdx.x * 128;
    const int c0 = blockIdx.y * 64;
    const int tid = threadIdx.x;
    const int lane = tid & 31;
    const int warp = tid >> 5;
    const int wm = warp & 3;
    const int wn = warp >> 2;
    const int g = lane >> 2;
    const int t = lane & 3;

    const __nv_bfloat16* Ag0 = A + (size_t)m0 * NN;
    const __nv_bfloat16* Bg0 = X + (size_t)c0 * NN;

    float acc[2][4][4];
    #pragma unroll
    for (int mi = 0; mi < 2; mi++)
        #pragma unroll
        for (int ni = 0; ni < 4; ni++)
            #pragma unroll
            for (int q = 0; q < 4; q++) acc[mi][ni][q] = 0.f;

    // per-thread staging coords (A: 1024 16B chunks, B: 512)
    int ar[4], ac[4], br[2], bc[2];
    #pragma unroll
    for (int i = 0; i < 4; i++) { int q = tid + i * 256; ar[i] = q >> 3; ac[i] = q & 7; }
    #pragma unroll
    for (int i = 0; i < 2; i++) { int q = tid + i * 256; br[i] = q >> 3; bc[i] = q & 7; }

    auto prefetch = [&](int kt, int buf) {
        char* sA = smem + (size_t)buf * STAGE_ELEMS * 2;
        char* sB = sA + 128 * A_ROW_W * 2;
        const __nv_bfloat16* Ags = Ag0 + kt * BK;
        const __nv_bfloat16* Bgs = Bg0 + kt * BK;
        #pragma unroll
        for (int i = 0; i < 4; i++)
            cp16(sA + ar[i] * 144 + ac[i] * 16, Ags + (size_t)ar[i] * NN + ac[i] * 8);
        #pragma unroll
        for (int i = 0; i < 2; i++)
            cp16(sB + br[i] * 144 + bc[i] * 16, Bgs + (size_t)br[i] * NN + bc[i] * 8);
    };

    prefetch(0, 0);
    asm volatile("cp.async.commit_group;\n");
    prefetch(1, 1);
    asm volatile("cp.async.commit_group;\n");

    int cur = 0;
    for (int kt = 0; kt < NT; kt++) {
        asm volatile("cp.async.wait_group 1;\n");
        __syncthreads();

        int pk = kt + 2;
        if (pk < NT) prefetch(pk, pk % STAGES);
        asm volatile("cp.async.commit_group;\n");

        const unsigned int* Aw =
            (const unsigned int*)(smem + (size_t)cur * STAGE_ELEMS * 2);
        const unsigned int* Bw = Aw + 128 * (A_ROW_W / 2);

        #pragma unroll
        for (int kk = 0; kk < 4; kk++) {
            const int kw = kk * 8 + t;
            unsigned int a[2][4], b[4][2];
            #pragma unroll
            for (int mi = 0; mi < 2; mi++) {
                int rb = (wm * 32 + mi * 16 + g) * 36;
                a[mi][0] = Aw[rb + kw];
                a[mi][1] = Aw[rb + 8 * 36 + kw];
                a[mi][2] = Aw[rb + kw + 4];
                a[mi][3] = Aw[rb + 8 * 36 + kw + 4];
            }
            #pragma unroll
            for (int ni = 0; ni < 4; ni++) {
                int nb = (wn * 32 + ni * 8 + g) * 36;
                b[ni][0] = Bw[nb + kw];
                b[ni][1] = Bw[nb + kw + 4];
            }
            #pragma unroll
            for (int mi = 0; mi < 2; mi++)
                #pragma unroll
                for (int ni = 0; ni < 4; ni++) {
                    asm volatile(
                        "mma.sync.aligned.m16n8k16.row.col.f32.bf16.bf16.f32 "
                        "{%0,%1,%2,%3}, {%4,%5,%6,%7}, {%8,%9}, {%0,%1,%2,%3};\n"
                        : "+f"(acc[mi][ni][0]), "+f"(acc[mi][ni][1]),
                          "+f"(acc[mi][ni][2]), "+f"(acc[mi][ni][3])
                        : "r"(a[mi][0]), "r"(a[mi][1]), "r"(a[mi][2]), "r"(a[mi][3]),
                          "r"(b[ni][0]), "r"(b[ni][1]));
                }
        }
        __syncthreads();
        cur = (cur + 1) % STAGES;
    }

    #pragma unroll
    for (int mi = 0; mi < 2; mi++) {
        int r0 = m0 + wm * 32 + mi * 16 + g;
        #pragma unroll
        for (int ni = 0; ni < 4; ni++) {
            int cc = c0 + wn * 32 + ni * 8 + t * 2;
            *(float2*)&Cb[(size_t)r0 * ncol + cc] =
                make_float2(acc[mi][ni][0], acc[mi][ni][1]);
            *(float2*)&Cb[(size_t)(r0 + 8) * ncol + cc] =
                make_float2(acc[mi][ni][2], acc[mi][ni][3]);
        }
    }
}

// ---------------------------------------------------------------- epi 1 ---
__global__ __launch_bounds__(256) void epi1(const float* __restrict__ state,
                                            const float* __restrict__ rk,
                                            const float* __restrict__ uk)
{
    __shared__ float srk[576], suk[576];
    for (int i = threadIdx.x; i < 576; i += 256) { srk[i] = rk[i]; suk[i] = uk[i]; }
    __syncthreads();

    int idx = blockIdx.x * blockDim.x + threadIdx.x;  // b*4096 + m
    int m = idx & 4095;
    int b = idx >> 12;

    float hs[36];
    #pragma unroll
    for (int s = 0; s < 2; s++) {
        const float* d = g_D1 + ((size_t)s * NN + m) * NCOL1 + b * 18;
        hs[s * 2 + 0] = d[0];
        hs[s * 2 + 1] = d[1];
        #pragma unroll
        for (int u = 0; u < 16; u++) hs[4 + s * 16 + u] = d[2 + u];
    }

    float aR[16], aU[16];
    #pragma unroll
    for (int u = 0; u < 16; u++) { aR[u] = 0.f; aU[u] = 0.f; }
    #pragma unroll
    for (int j = 0; j < 36; j++) {
        float h = hs[j];
        #pragma unroll
        for (int u = 0; u < 16; u++) {
            aR[u] = fmaf(h, srk[j * 16 + u], aR[u]);
            aU[u] = fmaf(h, suk[j * 16 + u], aU[u]);
        }
    }
    #pragma unroll
    for (int u = 0; u < 16; u++) {
        float r  = 1.f / (1.f + expf(-aR[u]));
        float uu = 1.f / (1.f + expf(-aU[u]));
        float pv = state[b * 65536 + u * 4096 + m];
        g_X2[(size_t)(b * 16 + u) * NN + m] = __float2bfloat16_rn(r * pv);
        g_U[(size_t)m * NCOL2 + b * 16 + u] = uu;
    }
    #pragma unroll
    for (int j = 0; j < 4; j++) g_H[(size_t)m * 256 + b * 4 + j] = hs[j];
}

// ---------------------------------------------------------------- epi 2 ---
__global__ __launch_bounds__(256) void epi2(const float* __restrict__ state,
                                            const float* __restrict__ ck,
                                            float* __restrict__ out)
{
    __shared__ float sck[576];
    for (int i = threadIdx.x; i < 576; i += 256) sck[i] = ck[i];
    __syncthreads();

    int idx = blockIdx.x * blockDim.x + threadIdx.x;  // b*4096 + m
    int m = idx & 4095;
    int b = idx >> 12;

    float hs[36];
    #pragma unroll
    for (int j = 0; j < 4; j++) hs[j] = g_H[(size_t)m * 256 + b * 4 + j];
    #pragma unroll
    for (int s = 0; s < 2; s++) {
        const float* d = g_D2 + ((size_t)s * NN + m) * NCOL2 + b * 16;
        #pragma unroll
        for (int u = 0; u < 16; u++) hs[4 + s * 16 + u] = d[u];
    }

    float aC[16];
    #pragma unroll
    for (int u = 0; u < 16; u++) aC[u] = 0.f;
    #pragma unroll
    for (int j = 0; j < 36; j++) {
        float h = hs[j];
        #pragma unroll
        for (int u = 0; u < 16; u++) aC[u] = fmaf(h, sck[j * 16 + u], aC[u]);
    }
    #pragma unroll
    for (int u = 0; u < 16; u++) {
        float c  = tanhf(aC[u]);
        float uu = g_U[(size_t)m * NCOL2 + b * 16 + u];
        float pv = state[b * 65536 + u * 4096 + m];
        out[b * 65536 + m * 16 + u] = uu * pv + (1.f - uu) * c;
    }
}

// -------------------------------------------------------------- launch ----
extern "C" void kernel_launch(void* const* d_in, const int* in_sizes, int n_in,
                              void* d_out, int out_size) {
    const float* inputs = (const float*)d_in[0];
    const float* state  = (const float*)d_in[1];
    const float* s0     = (const float*)d_in[2];
    const float* s1     = (const float*)d_in[3];
    const float* rk     = (const float*)d_in[4];
    const float* uk     = (const float*)d_in[5];
    const float* ck     = (const float*)d_in[6];
    float* out = (float*)d_out;

    static int smem_set = 0;
    if (!smem_set) {
        cudaFuncSetAttribute(gemm_bf16, cudaFuncAttributeMaxDynamicSharedMemorySize,
                             SMEM_BYTES);
        smem_set = 1;
    }

    __nv_bfloat16 *x1, *x2;
    float *d1, *d2;
    cudaGetSymbolAddress((void**)&x1, g_X1);
    cudaGetSymbolAddress((void**)&x2, g_X2);
    cudaGetSymbolAddress((void**)&d1, g_D1);
    cudaGetSymbolAddress((void**)&d2, g_D2);

    conv_sup<<<dim3(NN * NN / (256 * 8), 2), 256>>>(s0, s1);
    pack1<<<(NN * NCOL1) / 256, 256>>>(inputs, state);
    gemm_bf16<<<dim3(32, NCOL1 / 64, 2), 256, SMEM_BYTES>>>(x1, d1, NCOL1);
    epi1<<<(64 * NN) / 256, 256>>>(state, rk, uk);
    gemm_bf16<<<dim3(32, NCOL2 / 64, 2), 256, SMEM_BYTES>>>(x2, d2, NCOL2);
    epi2<<<(64 * NN) / 256, 256>>>(state, ck, out);
}

// round 5
// speedup vs baseline: 3.0637x; 1.3166x over previous
#include <cuda_runtime.h>
#include <cuda_bf16.h>
#include <cstdint>
#include <math.h>

// GCRNN cell: B=64, N=4096, F=2, U=16, S=2
// bf16 mma.sync m16n8k16, ldmatrix fragment loads, cp.async 3-stage,
// BM=128 BN=128 BK=64. GEMM output stored TRANSPOSED: D[z][col][m] so the
// gate epilogues read coalesced.

#define NN 4096
#define NCOL1 1152   // B*18
#define NCOL2 1024   // B*16
#define BM 128
#define BN 128
#define BKT 64
#define NT (NN / BKT)          // 64
#define ROW_B 144              // 64 bf16 + 8 pad = 144 bytes per smem row
#define A_BYTES (BM * ROW_B)   // 18432
#define STG_BYTES (2 * A_BYTES)
#define SMEM_TOT (3 * STG_BYTES)   // 110592

__device__ __nv_bfloat16 g_Sbf[2ull * NN * NN];      // supports bf16 row-major
__device__ __nv_bfloat16 g_X1[(size_t)NCOL1 * NN];   // col-major [col][n]
__device__ __nv_bfloat16 g_X2[(size_t)NCOL2 * NN];
__device__ float g_D1[2ull * NCOL1 * NN];            // [z][col][m]
__device__ float g_D2[2ull * NCOL2 * NN];            // [z][col][m]
__device__ float g_U[(size_t)NN * NCOL2];
__device__ float g_H[(size_t)NN * 256];

// ------------------------------------------------------------ convert ----
__global__ __launch_bounds__(256) void conv_sup(const float* __restrict__ S0,
                                                const float* __restrict__ S1) {
    const float* S = blockIdx.y ? S1 : S0;
    __nv_bfloat16* D = g_Sbf + (size_t)blockIdx.y * NN * NN;
    size_t idx = (size_t)blockIdx.x * 256 + threadIdx.x;
    float4 v0 = ((const float4*)S)[idx * 2];
    float4 v1 = ((const float4*)S)[idx * 2 + 1];
    __nv_bfloat162 p[4];
    p[0] = __floats2bfloat162_rn(v0.x, v0.y);
    p[1] = __floats2bfloat162_rn(v0.z, v0.w);
    p[2] = __floats2bfloat162_rn(v1.x, v1.y);
    p[3] = __floats2bfloat162_rn(v1.z, v1.w);
    ((uint4*)D)[idx] = *(uint4*)p;
}

// --------------------------------------------------------------- pack ----
__global__ __launch_bounds__(256) void pack1(const float* __restrict__ inputs,
                                             const float* __restrict__ state) {
    int idx = blockIdx.x * blockDim.x + threadIdx.x;
    int n = idx & 4095;
    int col = idx >> 12;              // 0..1151
    int b = col / 18;
    int c = col - b * 18;
    float v = (c < 2) ? inputs[b * 8192 + c * 4096 + n]
                      : state[b * 65536 + (c - 2) * 4096 + n];
    g_X1[(size_t)col * NN + n] = __float2bfloat16_rn(v);
}

// --------------------------------------------------------------- gemm ----
__device__ __forceinline__ void cp16s(uint32_t dst, const void* src) {
    asm volatile("cp.async.cg.shared.global [%0], [%1], 16;\n" :: "r"(dst), "l"(src));
}
__device__ __forceinline__ void ldsm4(unsigned* r, uint32_t addr) {
    asm volatile("ldmatrix.sync.aligned.m8n8.x4.shared.b16 {%0,%1,%2,%3}, [%4];"
                 : "=r"(r[0]), "=r"(r[1]), "=r"(r[2]), "=r"(r[3]) : "r"(addr));
}

// D[z][col][m] = sum_k S_z[m][k] * X[col][k]
__global__ __launch_bounds__(256) void gemm_bf16(
    const __nv_bfloat16* __restrict__ X, float* __restrict__ C, int ncol)
{
    extern __shared__ __align__(1024) char smem[];
    uint32_t sbase = (uint32_t)__cvta_generic_to_shared(smem);

    const __nv_bfloat16* A = g_Sbf + (size_t)blockIdx.z * NN * NN;
    float* Cb = C + (size_t)blockIdx.z * ncol * NN;
    const int m0 = blockIdx.x * BM;
    const int c0 = blockIdx.y * BN;
    const int tid = threadIdx.x;
    const int lane = tid & 31;
    const int warp = tid >> 5;
    const int wm = warp & 3;        // 4 x 32 rows
    const int wn = warp >> 2;       // 2 x 64 cols
    const int g = lane >> 2;
    const int t = lane & 3;

    const __nv_bfloat16* Ag0 = A + (size_t)m0 * NN;
    const __nv_bfloat16* Bg0 = X + (size_t)c0 * NN;

    float acc[2][8][4];
    #pragma unroll
    for (int mi = 0; mi < 2; mi++)
        #pragma unroll
        for (int ni = 0; ni < 8; ni++)
            #pragma unroll
            for (int q = 0; q < 4; q++) acc[mi][ni][q] = 0.f;

    // ldmatrix per-lane base offsets within a stage
    uint32_t aOff[2], bOff[4];
    #pragma unroll
    for (int mi = 0; mi < 2; mi++)
        aOff[mi] = (wm * 32 + mi * 16 + (lane & 15)) * ROW_B + ((lane >> 4) & 1) * 16;
    #pragma unroll
    for (int p = 0; p < 4; p++)
        bOff[p] = A_BYTES +
                  (wn * 64 + p * 16 + (lane & 7) + ((lane >> 4) & 1) * 8) * ROW_B +
                  ((lane >> 3) & 1) * 16;

    auto stage = [&](int kt, int buf) {
        uint32_t sA = sbase + buf * STG_BYTES;
        uint32_t sB = sA + A_BYTES;
        const __nv_bfloat16* Ags = Ag0 + kt * BKT;
        const __nv_bfloat16* Bgs = Bg0 + kt * BKT;
        #pragma unroll
        for (int i = 0; i < 4; i++) {
            int q = tid + i * 256;
            int r = q >> 3, c = q & 7;
            cp16s(sA + r * ROW_B + c * 16, Ags + (size_t)r * NN + c * 8);
            cp16s(sB + r * ROW_B + c * 16, Bgs + (size_t)r * NN + c * 8);
        }
    };

    stage(0, 0); asm volatile("cp.async.commit_group;\n" ::: "memory");
    stage(1, 1); asm volatile("cp.async.commit_group;\n" ::: "memory");

    int cur = 0;
    for (int kt = 0; kt < NT; kt++) {
        asm volatile("cp.async.wait_group 1;\n" ::: "memory");
        __syncthreads();

        int pk = kt + 2;
        if (pk < NT) stage(pk, pk % 3);
        asm volatile("cp.async.commit_group;\n" ::: "memory");

        uint32_t sb = sbase + cur * STG_BYTES;
        #pragma unroll
        for (int kk = 0; kk < 4; kk++) {
            unsigned a[2][4], b[8][2];
            #pragma unroll
            for (int mi = 0; mi < 2; mi++)
                ldsm4(a[mi], sb + aOff[mi] + kk * 32);
            #pragma unroll
            for (int p = 0; p < 4; p++) {
                unsigned r[4];
                ldsm4(r, sb + bOff[p] + kk * 32);
                b[2 * p][0] = r[0]; b[2 * p][1] = r[1];
                b[2 * p + 1][0] = r[2]; b[2 * p + 1][1] = r[3];
            }
            #pragma unroll
            for (int mi = 0; mi < 2; mi++)
                #pragma unroll
                for (int ni = 0; ni < 8; ni++) {
                    asm volatile(
                        "mma.sync.aligned.m16n8k16.row.col.f32.bf16.bf16.f32 "
                        "{%0,%1,%2,%3}, {%4,%5,%6,%7}, {%8,%9}, {%0,%1,%2,%3};\n"
                        : "+f"(acc[mi][ni][0]), "+f"(acc[mi][ni][1]),
                          "+f"(acc[mi][ni][2]), "+f"(acc[mi][ni][3])
                        : "r"(a[mi][0]), "r"(a[mi][1]), "r"(a[mi][2]), "r"(a[mi][3]),
                          "r"(b[ni][0]), "r"(b[ni][1]));
                }
        }
        __syncthreads();
        cur = (cur + 1) % 3;
    }

    // transposed store: D[col][m]
    #pragma unroll
    for (int mi = 0; mi < 2; mi++) {
        int r0 = m0 + wm * 32 + mi * 16 + g;
        #pragma unroll
        for (int ni = 0; ni < 8; ni++) {
            int cc = c0 + wn * 64 + ni * 8 + t * 2;
            Cb[(size_t)cc * NN + r0]           = acc[mi][ni][0];
            Cb[(size_t)(cc + 1) * NN + r0]     = acc[mi][ni][1];
            Cb[(size_t)cc * NN + r0 + 8]       = acc[mi][ni][2];
            Cb[(size_t)(cc + 1) * NN + r0 + 8] = acc[mi][ni][3];
        }
    }
}

// ---------------------------------------------------------------- epi 1 ---
__global__ __launch_bounds__(256) void epi1(const float* __restrict__ state,
                                            const float* __restrict__ rk,
                                            const float* __restrict__ uk)
{
    __shared__ float srk[576], suk[576];
    for (int i = threadIdx.x; i < 576; i += 256) { srk[i] = rk[i]; suk[i] = uk[i]; }
    __syncthreads();

    int idx = blockIdx.x * blockDim.x + threadIdx.x;  // b*4096 + m
    int m = idx & 4095;
    int b = idx >> 12;

    float hs[36];
    #pragma unroll
    for (int s = 0; s < 2; s++) {
        const float* d = g_D1 + ((size_t)(s * NCOL1 + b * 18)) * NN + m;
        hs[s * 2 + 0] = d[0];
        hs[s * 2 + 1] = d[(size_t)NN];
        #pragma unroll
        for (int u = 0; u < 16; u++) hs[4 + s * 16 + u] = d[(size_t)(2 + u) * NN];
    }

    float aR[16], aU[16];
    #pragma unroll
    for (int u = 0; u < 16; u++) { aR[u] = 0.f; aU[u] = 0.f; }
    #pragma unroll
    for (int j = 0; j < 36; j++) {
        float h = hs[j];
        #pragma unroll
        for (int u = 0; u < 16; u++) {
            aR[u] = fmaf(h, srk[j * 16 + u], aR[u]);
            aU[u] = fmaf(h, suk[j * 16 + u], aU[u]);
        }
    }
    #pragma unroll
    for (int u = 0; u < 16; u++) {
        float r  = 1.f / (1.f + expf(-aR[u]));
        float uu = 1.f / (1.f + expf(-aU[u]));
        float pv = state[b * 65536 + u * 4096 + m];
        g_X2[(size_t)(b * 16 + u) * NN + m] = __float2bfloat16_rn(r * pv);
        g_U[(size_t)m * NCOL2 + b * 16 + u] = uu;
    }
    #pragma unroll
    for (int j = 0; j < 4; j++) g_H[(size_t)m * 256 + b * 4 + j] = hs[j];
}

// ---------------------------------------------------------------- epi 2 ---
__global__ __launch_bounds__(256) void epi2(const float* __restrict__ state,
                                            const float* __restrict__ ck,
                                            float* __restrict__ out)
{
    __shared__ float sck[576];
    for (int i = threadIdx.x; i < 576; i += 256) sck[i] = ck[i];
    __syncthreads();

    int idx = blockIdx.x * blockDim.x + threadIdx.x;  // b*4096 + m
    int m = idx & 4095;
    int b = idx >> 12;

    float hs[36];
    #pragma unroll
    for (int j = 0; j < 4; j++) hs[j] = g_H[(size_t)m * 256 + b * 4 + j];
    #pragma unroll
    for (int s = 0; s < 2; s++) {
        const float* d = g_D2 + ((size_t)(s * NCOL2 + b * 16)) * NN + m;
        #pragma unroll
        for (int u = 0; u < 16; u++) hs[4 + s * 16 + u] = d[(size_t)u * NN];
    }

    float aC[16];
    #pragma unroll
    for (int u = 0; u < 16; u++) aC[u] = 0.f;
    #pragma unroll
    for (int j = 0; j < 36; j++) {
        float h = hs[j];
        #pragma unroll
        for (int u = 0; u < 16; u++) aC[u] = fmaf(h, sck[j * 16 + u], aC[u]);
    }
    float4 o[4];
    #pragma unroll
    for (int u = 0; u < 16; u++) {
        float c  = tanhf(aC[u]);
        float uu = g_U[(size_t)m * NCOL2 + b * 16 + u];
        float pv = state[b * 65536 + u * 4096 + m];
        ((float*)o)[u] = uu * pv + (1.f - uu) * c;
    }
    float4* dst = (float4*)&out[b * 65536 + m * 16];
    #pragma unroll
    for (int q = 0; q < 4; q++) dst[q] = o[q];
}

// -------------------------------------------------------------- launch ----
extern "C" void kernel_launch(void* const* d_in, const int* in_sizes, int n_in,
                              void* d_out, int out_size) {
    const float* inputs = (const float*)d_in[0];
    const float* state  = (const float*)d_in[1];
    const float* s0     = (const float*)d_in[2];
    const float* s1     = (const float*)d_in[3];
    const float* rk     = (const float*)d_in[4];
    const float* uk     = (const float*)d_in[5];
    const float* ck     = (const float*)d_in[6];
    float* out = (float*)d_out;

    cudaFuncSetAttribute(gemm_bf16, cudaFuncAttributeMaxDynamicSharedMemorySize,
                         SMEM_TOT);

    __nv_bfloat16 *x1, *x2;
    float *d1, *d2;
    cudaGetSymbolAddress((void**)&x1, g_X1);
    cudaGetSymbolAddress((void**)&x2, g_X2);
    cudaGetSymbolAddress((void**)&d1, g_D1);
    cudaGetSymbolAddress((void**)&d2, g_D2);

    conv_sup<<<dim3(NN * NN / (256 * 8), 2), 256>>>(s0, s1);
    pack1<<<(NN * NCOL1) / 256, 256>>>(inputs, state);
    gemm_bf16<<<dim3(NN / BM, NCOL1 / BN, 2), 256, SMEM_TOT>>>(x1, d1, NCOL1);
    epi1<<<(64 * NN) / 256, 256>>>(state, rk, uk);
    gemm_bf16<<<dim3(NN / BM, NCOL2 / BN, 2), 256, SMEM_TOT>>>(x2, d2, NCOL2);
    epi2<<<(64 * NN) / 256, 256>>>(state, ck, out);
}

// round 6
// speedup vs baseline: 3.1958x; 1.0431x over previous
#include <cuda_runtime.h>
#include <cuda_bf16.h>
#include <cstdint>
#include <math.h>

// GCRNN cell: B=64, N=4096, F=2, U=16, S=2
// bf16 mma.sync m16n8k16, ldmatrix, cp.async 2-stage ping-pong (2 CTA/SM),
// BM=128 BN=128 BK=64. GEMM output transposed D[z][col][m]; aux arrays U,H
// also stored [col][m] so epilogue traffic is fully coalesced.

#define NN 4096
#define NCOL1 1152   // B*18
#define NCOL2 1024   // B*16
#define BM 128
#define BN 128
#define BKT 64
#define NT (NN / BKT)          // 64
#define ROW_B 144              // 64 bf16 + 8 pad = 144 bytes per smem row
#define A_BYTES (BM * ROW_B)   // 18432
#define STG_BYTES (2 * A_BYTES)
#define SMEM_TOT (2 * STG_BYTES)   // 73728 -> 2 CTAs/SM

__device__ __nv_bfloat16 g_Sbf[2ull * NN * NN];      // supports bf16 row-major
__device__ __nv_bfloat16 g_X1[(size_t)NCOL1 * NN];   // col-major [col][n]
__device__ __nv_bfloat16 g_X2[(size_t)NCOL2 * NN];
__device__ float g_D1[2ull * NCOL1 * NN];            // [z][col][m]
__device__ float g_D2[2ull * NCOL2 * NN];            // [z][col][m]
__device__ float g_U[(size_t)NCOL2 * NN];            // [b*16+u][m]
__device__ float g_H[(size_t)256 * NN];              // [b*4+j][m]

// ------------------------------------------------------------ convert ----
__global__ __launch_bounds__(256) void conv_sup(const float* __restrict__ S0,
                                                const float* __restrict__ S1) {
    const float* S = blockIdx.y ? S1 : S0;
    __nv_bfloat16* D = g_Sbf + (size_t)blockIdx.y * NN * NN;
    size_t idx = (size_t)blockIdx.x * 256 + threadIdx.x;
    float4 v0 = ((const float4*)S)[idx * 2];
    float4 v1 = ((const float4*)S)[idx * 2 + 1];
    __nv_bfloat162 p[4];
    p[0] = __floats2bfloat162_rn(v0.x, v0.y);
    p[1] = __floats2bfloat162_rn(v0.z, v0.w);
    p[2] = __floats2bfloat162_rn(v1.x, v1.y);
    p[3] = __floats2bfloat162_rn(v1.z, v1.w);
    ((uint4*)D)[idx] = *(uint4*)p;
}

// --------------------------------------------------------------- pack ----
__global__ __launch_bounds__(256) void pack1(const float* __restrict__ inputs,
                                             const float* __restrict__ state) {
    int idx = blockIdx.x * blockDim.x + threadIdx.x;
    int n = idx & 4095;
    int col = idx >> 12;              // 0..1151
    int b = col / 18;
    int c = col - b * 18;
    float v = (c < 2) ? inputs[b * 8192 + c * 4096 + n]
                      : state[b * 65536 + (c - 2) * 4096 + n];
    g_X1[(size_t)col * NN + n] = __float2bfloat16_rn(v);
}

// --------------------------------------------------------------- gemm ----
__device__ __forceinline__ void cp16s(uint32_t dst, const void* src) {
    asm volatile("cp.async.cg.shared.global [%0], [%1], 16;\n" :: "r"(dst), "l"(src));
}
__device__ __forceinline__ void ldsm4(unsigned* r, uint32_t addr) {
    asm volatile("ldmatrix.sync.aligned.m8n8.x4.shared.b16 {%0,%1,%2,%3}, [%4];"
                 : "=r"(r[0]), "=r"(r[1]), "=r"(r[2]), "=r"(r[3]) : "r"(addr));
}

// D[z][col][m] = sum_k S_z[m][k] * X[col][k]
__global__ __launch_bounds__(256) void gemm_bf16(
    const __nv_bfloat16* __restrict__ X, float* __restrict__ C, int ncol)
{
    extern __shared__ __align__(1024) char smem[];
    uint32_t sbase = (uint32_t)__cvta_generic_to_shared(smem);

    const __nv_bfloat16* A = g_Sbf + (size_t)blockIdx.z * NN * NN;
    float* Cb = C + (size_t)blockIdx.z * ncol * NN;
    const int m0 = blockIdx.x * BM;
    const int c0 = blockIdx.y * BN;
    const int tid = threadIdx.x;
    const int lane = tid & 31;
    const int warp = tid >> 5;
    const int wm = warp & 3;        // 4 x 32 rows
    const int wn = warp >> 2;       // 2 x 64 cols
    const int g = lane >> 2;
    const int t = lane & 3;

    const __nv_bfloat16* Ag0 = A + (size_t)m0 * NN;
    const __nv_bfloat16* Bg0 = X + (size_t)c0 * NN;

    float acc[2][8][4];
    #pragma unroll
    for (int mi = 0; mi < 2; mi++)
        #pragma unroll
        for (int ni = 0; ni < 8; ni++)
            #pragma unroll
            for (int q = 0; q < 4; q++) acc[mi][ni][q] = 0.f;

    uint32_t aOff[2], bOff[4];
    #pragma unroll
    for (int mi = 0; mi < 2; mi++)
        aOff[mi] = (wm * 32 + mi * 16 + (lane & 15)) * ROW_B + ((lane >> 4) & 1) * 16;
    #pragma unroll
    for (int p = 0; p < 4; p++)
        bOff[p] = A_BYTES +
                  (wn * 64 + p * 16 + (lane & 7) + ((lane >> 4) & 1) * 8) * ROW_B +
                  ((lane >> 3) & 1) * 16;

    auto stage = [&](int kt, int buf) {
        uint32_t sA = sbase + buf * STG_BYTES;
        uint32_t sB = sA + A_BYTES;
        const __nv_bfloat16* Ags = Ag0 + kt * BKT;
        const __nv_bfloat16* Bgs = Bg0 + kt * BKT;
        #pragma unroll
        for (int i = 0; i < 4; i++) {
            int q = tid + i * 256;
            int r = q >> 3, c = q & 7;
            cp16s(sA + r * ROW_B + c * 16, Ags + (size_t)r * NN + c * 8);
            cp16s(sB + r * ROW_B + c * 16, Bgs + (size_t)r * NN + c * 8);
        }
    };

    stage(0, 0);
    asm volatile("cp.async.commit_group;\n" ::: "memory");

    for (int kt = 0; kt < NT; kt++) {
        int nxt = kt + 1;
        if (nxt < NT) {
            stage(nxt, nxt & 1);
            asm volatile("cp.async.commit_group;\n" ::: "memory");
            asm volatile("cp.async.wait_group 1;\n" ::: "memory");
        } else {
            asm volatile("cp.async.wait_group 0;\n" ::: "memory");
        }
        __syncthreads();

        uint32_t sb = sbase + (kt & 1) * STG_BYTES;
        #pragma unroll
        for (int kk = 0; kk < 4; kk++) {
            unsigned a[2][4], b[8][2];
            #pragma unroll
            for (int mi = 0; mi < 2; mi++)
                ldsm4(a[mi], sb + aOff[mi] + kk * 32);
            #pragma unroll
            for (int p = 0; p < 4; p++) {
                unsigned r[4];
                ldsm4(r, sb + bOff[p] + kk * 32);
                b[2 * p][0] = r[0]; b[2 * p][1] = r[1];
                b[2 * p + 1][0] = r[2]; b[2 * p + 1][1] = r[3];
            }
            #pragma unroll
            for (int mi = 0; mi < 2; mi++)
                #pragma unroll
                for (int ni = 0; ni < 8; ni++) {
                    asm volatile(
                        "mma.sync.aligned.m16n8k16.row.col.f32.bf16.bf16.f32 "
                        "{%0,%1,%2,%3}, {%4,%5,%6,%7}, {%8,%9}, {%0,%1,%2,%3};\n"
                        : "+f"(acc[mi][ni][0]), "+f"(acc[mi][ni][1]),
                          "+f"(acc[mi][ni][2]), "+f"(acc[mi][ni][3])
                        : "r"(a[mi][0]), "r"(a[mi][1]), "r"(a[mi][2]), "r"(a[mi][3]),
                          "r"(b[ni][0]), "r"(b[ni][1]));
                }
        }
        __syncthreads();
    }

    // transposed store: D[col][m]
    #pragma unroll
    for (int mi = 0; mi < 2; mi++) {
        int r0 = m0 + wm * 32 + mi * 16 + g;
        #pragma unroll
        for (int ni = 0; ni < 8; ni++) {
            int cc = c0 + wn * 64 + ni * 8 + t * 2;
            Cb[(size_t)cc * NN + r0]           = acc[mi][ni][0];
            Cb[(size_t)(cc + 1) * NN + r0]     = acc[mi][ni][1];
            Cb[(size_t)cc * NN + r0 + 8]       = acc[mi][ni][2];
            Cb[(size_t)(cc + 1) * NN + r0 + 8] = acc[mi][ni][3];
        }
    }
}

// ---------------------------------------------------------------- epi 1 ---
__global__ __launch_bounds__(256) void epi1(const float* __restrict__ state,
                                            const float* __restrict__ rk,
                                            const float* __restrict__ uk)
{
    __shared__ float srk[576], suk[576];
    for (int i = threadIdx.x; i < 576; i += 256) { srk[i] = rk[i]; suk[i] = uk[i]; }
    __syncthreads();

    int idx = blockIdx.x * blockDim.x + threadIdx.x;  // b*4096 + m
    int m = idx & 4095;
    int b = idx >> 12;

    float hs[36];
    #pragma unroll
    for (int s = 0; s < 2; s++) {
        const float* d = g_D1 + ((size_t)(s * NCOL1 + b * 18)) * NN + m;
        hs[s * 2 + 0] = d[0];
        hs[s * 2 + 1] = d[(size_t)NN];
        #pragma unroll
        for (int u = 0; u < 16; u++) hs[4 + s * 16 + u] = d[(size_t)(2 + u) * NN];
    }

    float aR[16], aU[16];
    #pragma unroll
    for (int u = 0; u < 16; u++) { aR[u] = 0.f; aU[u] = 0.f; }
    #pragma unroll
    for (int j = 0; j < 36; j++) {
        float h = hs[j];
        #pragma unroll
        for (int u = 0; u < 16; u++) {
            aR[u] = fmaf(h, srk[j * 16 + u], aR[u]);
            aU[u] = fmaf(h, suk[j * 16 + u], aU[u]);
        }
    }
    #pragma unroll
    for (int u = 0; u < 16; u++) {
        float r  = 1.f / (1.f + expf(-aR[u]));
        float uu = 1.f / (1.f + expf(-aU[u]));
        float pv = state[b * 65536 + u * 4096 + m];
        g_X2[(size_t)(b * 16 + u) * NN + m] = __float2bfloat16_rn(r * pv);
        g_U[(size_t)(b * 16 + u) * NN + m] = uu;
    }
    #pragma unroll
    for (int j = 0; j < 4; j++) g_H[(size_t)(b * 4 + j) * NN + m] = hs[j];
}

// ---------------------------------------------------------------- epi 2 ---
__global__ __launch_bounds__(256) void epi2(const float* __restrict__ state,
                                            const float* __restrict__ ck,
                                            float* __restrict__ out)
{
    __shared__ float sck[576];
    for (int i = threadIdx.x; i < 576; i += 256) sck[i] = ck[i];
    __syncthreads();

    int idx = blockIdx.x * blockDim.x + threadIdx.x;  // b*4096 + m
    int m = idx & 4095;
    int b = idx >> 12;

    float hs[36];
    #pragma unroll
    for (int j = 0; j < 4; j++) hs[j] = g_H[(size_t)(b * 4 + j) * NN + m];
    #pragma unroll
    for (int s = 0; s < 2; s++) {
        const float* d = g_D2 + ((size_t)(s * NCOL2 + b * 16)) * NN + m;
        #pragma unroll
        for (int u = 0; u < 16; u++) hs[4 + s * 16 + u] = d[(size_t)u * NN];
    }

    float aC[16];
    #pragma unroll
    for (int u = 0; u < 16; u++) aC[u] = 0.f;
    #pragma unroll
    for (int j = 0; j < 36; j++) {
        float h = hs[j];
        #pragma unroll
        for (int u = 0; u < 16; u++) aC[u] = fmaf(h, sck[j * 16 + u], aC[u]);
    }
    float4 o[4];
    #pragma unroll
    for (int u = 0; u < 16; u++) {
        float c  = tanhf(aC[u]);
        float uu = g_U[(size_t)(b * 16 + u) * NN + m];
        float pv = state[b * 65536 + u * 4096 + m];
        ((float*)o)[u] = uu * pv + (1.f - uu) * c;
    }
    float4* dst = (float4*)&out[b * 65536 + m * 16];
    #pragma unroll
    for (int q = 0; q < 4; q++) dst[q] = o[q];
}

// -------------------------------------------------------------- launch ----
extern "C" void kernel_launch(void* const* d_in, const int* in_sizes, int n_in,
                              void* d_out, int out_size) {
    const float* inputs = (const float*)d_in[0];
    const float* state  = (const float*)d_in[1];
    const float* s0     = (const float*)d_in[2];
    const float* s1     = (const float*)d_in[3];
    const float* rk     = (const float*)d_in[4];
    const float* uk     = (const float*)d_in[5];
    const float* ck     = (const float*)d_in[6];
    float* out = (float*)d_out;

    cudaFuncSetAttribute(gemm_bf16, cudaFuncAttributeMaxDynamicSharedMemorySize,
                         SMEM_TOT);

    __nv_bfloat16 *x1, *x2;
    float *d1, *d2;
    cudaGetSymbolAddress((void**)&x1, g_X1);
    cudaGetSymbolAddress((void**)&x2, g_X2);
    cudaGetSymbolAddress((void**)&d1, g_D1);
    cudaGetSymbolAddress((void**)&d2, g_D2);

    conv_sup<<<dim3(NN * NN / (256 * 8), 2), 256>>>(s0, s1);
    pack1<<<(NN * NCOL1) / 256, 256>>>(inputs, state);
    gemm_bf16<<<dim3(NN / BM, NCOL1 / BN, 2), 256, SMEM_TOT>>>(x1, d1, NCOL1);
    epi1<<<(64 * NN) / 256, 256>>>(state, rk, uk);
    gemm_bf16<<<dim3(NN / BM, NCOL2 / BN, 2), 256, SMEM_TOT>>>(x2, d2, NCOL2);
    epi2<<<(64 * NN) / 256, 256>>>(state, ck, out);
}